// round 16
// baseline (speedup 1.0000x reference)
#include <cuda_runtime.h>
#include <math.h>

#define NNODES 65536
#define NEDGES (NNODES * 16)
#define NEG 0.2f
#define MAXD 128   // per-warp edge cache; deg ~ Poisson(16), P(deg>128) ~ 0

// packed fp32x2 FMA (Blackwell FFMA2)
#define FMA2(d, a, b) asm("fma.rn.f32x2 %0, %1, %2, %0;" : "+l"(d) : "l"(a), "l"(b))
#define PACK2(d, s)   asm("mov.b64 %0, {%1, %1};" : "=l"(d) : "f"(s))

// ---------------- scratch (static device globals; no runtime alloc) --------
__device__ __align__(16) float g_H[NNODES * 256];
__device__ __align__(16) float g_A[NNODES * 256];
__device__ __align__(8)  float g_als[NNODES * 2];
__device__ __align__(8)  float g_ald[NNODES * 2];
__device__ __align__(16) float g_WxA[4][336 * 256];  // per-layer extended weights
__device__ int g_cnt[NNODES];          // zero-init at load; k_scan re-zeroes each call
__device__ int g_off[NNODES + 1];
__device__ int g_cur[NNODES];
__device__ int g_col[NEDGES];

// ---------------- CSR build ------------------------------------------------
__global__ void k_count(const int* __restrict__ dst) {
    int e = blockIdx.x * blockDim.x + threadIdx.x;
    if (e < NEDGES) atomicAdd(&g_cnt[dst[e]], 1);
}

// exclusive scan of counts; seeds g_cur; self-clears g_cnt for the next replay
__global__ void k_scan() {
    __shared__ int ss[1024];
    int t = threadIdx.x;
    int base = t * 64;
    int s = 0;
#pragma unroll 8
    for (int i = 0; i < 64; i++) s += g_cnt[base + i];
    ss[t] = s;
    __syncthreads();
    for (int d = 1; d < 1024; d <<= 1) {
        int v = (t >= d) ? ss[t - d] : 0;
        __syncthreads();
        ss[t] += v;
        __syncthreads();
    }
    int run = (t == 0) ? 0 : ss[t - 1];
    for (int i = 0; i < 64; i++) {
        g_off[base + i] = run;
        g_cur[base + i] = run;
        run += g_cnt[base + i];
        g_cnt[base + i] = 0;          // self-clear for next graph replay
    }
    if (t == 1023) g_off[NNODES] = run;
}

__global__ void k_fill(const int* __restrict__ src, const int* __restrict__ dst) {
    int e = blockIdx.x * blockDim.x + threadIdx.x;
    if (e < NEDGES) {
        int d = dst[e];
        int p = atomicAdd(&g_cur[d], 1);
        g_col[p] = src[e];
    }
}

// ---------------- all-layer W-extension prep: Wx_l = [W_l | W@as | W@ad] ---
__global__ void k_prep_all(
    const float* __restrict__ W0, const float* __restrict__ as0, const float* __restrict__ ad0,
    const float* __restrict__ W1, const float* __restrict__ as1, const float* __restrict__ ad1,
    const float* __restrict__ W2, const float* __restrict__ as2, const float* __restrict__ ad2,
    const float* __restrict__ W3, const float* __restrict__ as3, const float* __restrict__ ad3)
{
    const float* Ws[4] = {W0, W1, W2, W3};
    const float* As[4] = {as0, as1, as2, as3};
    const float* Ad[4] = {ad0, ad1, ad2, ad3};
    const int Ks[4] = {336, 250, 150, 100};
    const int Cs[4] = {125, 75, 50, 30};
    int k = (blockIdx.x * blockDim.x + threadIdx.x) >> 5;
    int lane = threadIdx.x & 31;
#pragma unroll
    for (int l = 0; l < 4; l++) {
        if (k >= Ks[l]) continue;
        int C = Cs[l], HC = 2 * C;
        const float* wp = Ws[l] + (size_t)k * HC;
        float* xp = g_WxA[l] + (size_t)k * (HC + 4);
        float s0 = 0, s1 = 0, d0 = 0, d1 = 0;
        for (int c = lane; c < HC; c += 32) {
            float wv = wp[c];
            xp[c] = wv;
            float a = As[l][c], b = Ad[l][c];
            if (c < C) { s0 = fmaf(wv, a, s0); d0 = fmaf(wv, b, d0); }
            else       { s1 = fmaf(wv, a, s1); d1 = fmaf(wv, b, d1); }
        }
#pragma unroll
        for (int o = 16; o; o >>= 1) {
            s0 += __shfl_xor_sync(0xffffffffu, s0, o);
            s1 += __shfl_xor_sync(0xffffffffu, s1, o);
            d0 += __shfl_xor_sync(0xffffffffu, d0, o);
            d1 += __shfl_xor_sync(0xffffffffu, d1, o);
        }
        if (lane == 0) {
            xp[HC] = s0; xp[HC + 1] = s1; xp[HC + 2] = d0; xp[HC + 3] = d1;
        }
    }
}

// ---------------- SGEMM, FFMA2, 16x4 per-thread tile (R12 champion) --------
// Columns >= NH are attention-logit columns, routed to g_als / g_ald.
template <bool RELU, bool BIAS>
__global__ void __launch_bounds__(256) k_sgemm(
    const float* __restrict__ A, const float* __restrict__ B,
    const float* __restrict__ bias, float* __restrict__ C,
    int M, int N, int K, int lda, int ldb, int ldc,
    float* als, float* ald, int NH)
{
    constexpr int BM = 256, BN = 64, BK = 16, ASTR = 260;
    __shared__ float As[BK * ASTR];
    __shared__ float Bs[BK * BN];

    int tid = threadIdx.x;
    int tx = tid & 15;
    int ty = tid >> 4;
    int bm = blockIdx.y * BM;
    int bn = blockIdx.x * BN;
    int kq = tid & 3, ma = tid >> 2;

    unsigned long long acc[8][4];
#pragma unroll
    for (int i = 0; i < 8; i++)
#pragma unroll
        for (int j = 0; j < 4; j++) acc[i][j] = 0ull;

    int ntiles = (K + BK - 1) / BK;
    float4 pa[4];
    float pb[4];

    {
        int kk = kq * 4;
#pragma unroll
        for (int r = 0; r < 4; r++) {
            int row = bm + ma + r * 64;
            if (kk + 3 < K) {
                pa[r] = __ldcs((const float4*)(A + (size_t)row * lda + kk));
            } else {
                float4 v = make_float4(0.f, 0.f, 0.f, 0.f);
                if (kk     < K) v.x = __ldcs(A + (size_t)row * lda + kk);
                if (kk + 1 < K) v.y = __ldcs(A + (size_t)row * lda + kk + 1);
                if (kk + 2 < K) v.z = __ldcs(A + (size_t)row * lda + kk + 2);
                pa[r] = v;
            }
        }
#pragma unroll
        for (int i = 0; i < 4; i++) {
            int idx = tid + i * 256;
            int n = idx & 63, k = idx >> 6;
            int col = bn + n;
            pb[i] = (k < K && col < N) ? B[(size_t)k * ldb + col] : 0.f;
        }
    }

    for (int t = 0; t < ntiles; t++) {
        __syncthreads();
#pragma unroll
        for (int r = 0; r < 4; r++) {
            float v[4] = {pa[r].x, pa[r].y, pa[r].z, pa[r].w};
#pragma unroll
            for (int j = 0; j < 4; j++)
                As[(kq * 4 + j) * ASTR + ma + r * 64] = v[j];
        }
#pragma unroll
        for (int i = 0; i < 4; i++) {
            int idx = tid + i * 256;
            Bs[(idx >> 6) * BN + (idx & 63)] = pb[i];
        }
        __syncthreads();

        if (t + 1 < ntiles) {
            int kk = (t + 1) * BK + kq * 4;
#pragma unroll
            for (int r = 0; r < 4; r++) {
                int row = bm + ma + r * 64;
                if (kk + 3 < K) {
                    pa[r] = __ldcs((const float4*)(A + (size_t)row * lda + kk));
                } else {
                    float4 v = make_float4(0.f, 0.f, 0.f, 0.f);
                    if (kk     < K) v.x = __ldcs(A + (size_t)row * lda + kk);
                    if (kk + 1 < K) v.y = __ldcs(A + (size_t)row * lda + kk + 1);
                    if (kk + 2 < K) v.z = __ldcs(A + (size_t)row * lda + kk + 2);
                    pa[r] = v;
                }
            }
#pragma unroll
            for (int i = 0; i < 4; i++) {
                int idx = tid + i * 256;
                int n = idx & 63, k = (t + 1) * BK + (idx >> 6);
                int col = bn + n;
                pb[i] = (k < K && col < N) ? B[(size_t)k * ldb + col] : 0.f;
            }
        }

#pragma unroll
        for (int kk = 0; kk < BK; kk++) {
            const ulonglong2* ap = (const ulonglong2*)&As[kk * ASTR + ty * 16];
            unsigned long long aa[8];
#pragma unroll
            for (int q = 0; q < 4; q++) {
                ulonglong2 u = ap[q];
                aa[2 * q] = u.x; aa[2 * q + 1] = u.y;
            }
            float4 b4 = *(const float4*)&Bs[kk * BN + tx * 4];
            unsigned long long bb[4];
            PACK2(bb[0], b4.x); PACK2(bb[1], b4.y);
            PACK2(bb[2], b4.z); PACK2(bb[3], b4.w);
#pragma unroll
            for (int i = 0; i < 8; i++)
#pragma unroll
                for (int j = 0; j < 4; j++)
                    FMA2(acc[i][j], aa[i], bb[j]);
        }
    }

#pragma unroll
    for (int i = 0; i < 8; i++) {
#pragma unroll
        for (int j = 0; j < 4; j++) {
            int col = bn + tx * 4 + j;
            if (col < N) {
                float lo = __uint_as_float((unsigned)(acc[i][j] & 0xffffffffull));
                float hi = __uint_as_float((unsigned)(acc[i][j] >> 32));
                int row = bm + ty * 16 + 2 * i;
                if (col < NH) {
                    float bv = BIAS ? bias[col] : 0.f;
                    float v0 = lo + bv, v1 = hi + bv;
                    if (RELU) { v0 = fmaxf(v0, 0.f); v1 = fmaxf(v1, 0.f); }
                    C[(size_t)row * ldc + col]       = v0;
                    C[(size_t)(row + 1) * ldc + col] = v1;
                } else {
                    int q = col - NH;             // 0,1 -> als ; 2,3 -> ald
                    float* dp = (q < 2) ? als : ald;
                    int h = q & 1;
                    dp[2 * row + h]       = lo;
                    dp[2 * (row + 1) + h] = hi;
                }
            }
        }
    }
}

// ---------------- small-tile SGEMM for the MLP head (BM=64, full-chip grid) -
// 256 threads; A tile = exactly one float4/thread; 4x4 per-thread tile.
template <bool RELU>
__global__ void __launch_bounds__(256) k_sgemm64(
    const float* __restrict__ A, const float* __restrict__ B,
    const float* __restrict__ bias, float* __restrict__ C,
    int N, int K, int lda, int ldb, int ldc)
{
    constexpr int BN = 64, BK = 16, ASTR = 68;
    __shared__ float As[BK * ASTR];
    __shared__ float Bs[BK * BN];

    int tid = threadIdx.x;
    int tx = tid & 15;
    int ty = tid >> 4;
    int bm = blockIdx.y * 64;
    int bn = blockIdx.x * BN;
    int kq = tid & 3, ma = tid >> 2;   // ma in [0,64): one float4 per thread

    unsigned long long acc[2][4];
#pragma unroll
    for (int i = 0; i < 2; i++)
#pragma unroll
        for (int j = 0; j < 4; j++) acc[i][j] = 0ull;

    int ntiles = (K + BK - 1) / BK;
    float4 pa;
    float pb[4];

    {
        int kk = kq * 4;
        int row = bm + ma;
        if (kk + 3 < K) {
            pa = *(const float4*)(A + (size_t)row * lda + kk);
        } else {
            float4 v = make_float4(0.f, 0.f, 0.f, 0.f);
            if (kk     < K) v.x = A[(size_t)row * lda + kk];
            if (kk + 1 < K) v.y = A[(size_t)row * lda + kk + 1];
            if (kk + 2 < K) v.z = A[(size_t)row * lda + kk + 2];
            pa = v;
        }
#pragma unroll
        for (int i = 0; i < 4; i++) {
            int idx = tid + i * 256;
            int n = idx & 63, k = idx >> 6;
            int col = bn + n;
            pb[i] = (k < K && col < N) ? B[(size_t)k * ldb + col] : 0.f;
        }
    }

    for (int t = 0; t < ntiles; t++) {
        __syncthreads();
        {
            float v[4] = {pa.x, pa.y, pa.z, pa.w};
#pragma unroll
            for (int j = 0; j < 4; j++)
                As[(kq * 4 + j) * ASTR + ma] = v[j];
        }
#pragma unroll
        for (int i = 0; i < 4; i++) {
            int idx = tid + i * 256;
            Bs[(idx >> 6) * BN + (idx & 63)] = pb[i];
        }
        __syncthreads();

        if (t + 1 < ntiles) {
            int kk = (t + 1) * BK + kq * 4;
            int row = bm + ma;
            if (kk + 3 < K) {
                pa = *(const float4*)(A + (size_t)row * lda + kk);
            } else {
                float4 v = make_float4(0.f, 0.f, 0.f, 0.f);
                if (kk     < K) v.x = A[(size_t)row * lda + kk];
                if (kk + 1 < K) v.y = A[(size_t)row * lda + kk + 1];
                if (kk + 2 < K) v.z = A[(size_t)row * lda + kk + 2];
                pa = v;
            }
#pragma unroll
            for (int i = 0; i < 4; i++) {
                int idx = tid + i * 256;
                int n = idx & 63, k = (t + 1) * BK + (idx >> 6);
                int col = bn + n;
                pb[i] = (k < K && col < N) ? B[(size_t)k * ldb + col] : 0.f;
            }
        }

#pragma unroll
        for (int kk = 0; kk < BK; kk++) {
            ulonglong2 u = *(const ulonglong2*)&As[kk * ASTR + ty * 4];
            float4 b4 = *(const float4*)&Bs[kk * BN + tx * 4];
            unsigned long long bb[4];
            PACK2(bb[0], b4.x); PACK2(bb[1], b4.y);
            PACK2(bb[2], b4.z); PACK2(bb[3], b4.w);
#pragma unroll
            for (int j = 0; j < 4; j++) {
                FMA2(acc[0][j], u.x, bb[j]);
                FMA2(acc[1][j], u.y, bb[j]);
            }
        }
    }

#pragma unroll
    for (int i = 0; i < 2; i++) {
#pragma unroll
        for (int j = 0; j < 4; j++) {
            int col = bn + tx * 4 + j;
            if (col < N) {
                float lo = __uint_as_float((unsigned)(acc[i][j] & 0xffffffffull));
                float hi = __uint_as_float((unsigned)(acc[i][j] >> 32));
                float bv = bias[col];
                float v0 = lo + bv, v1 = hi + bv;
                if (RELU) { v0 = fmaxf(v0, 0.f); v1 = fmaxf(v1, 0.f); }
                int row = bm + ty * 4 + 2 * i;
                C[(size_t)row * ldc + col]       = v0;
                C[(size_t)(row + 1) * ldc + col] = v1;
            }
        }
    }
}

__device__ __forceinline__ float lrelu(float x) { return x > 0.f ? x : NEG * x; }

// ---------------- aggregation: smem edge cache (R12 champion config) -------
template <int R4>
__global__ void __launch_bounds__(256) k_agg(
    const float* __restrict__ h, const float* __restrict__ bias,
    float* __restrict__ out, int C, int HC, int ld)
{
    constexpr int EB = (R4 == 1) ? 8 : 4;   // edges per batch (proven sweet spot)
    __shared__ float2 s_ew[8][MAXD];
    __shared__ int    s_col[8][MAXD];
    int wip = threadIdx.x >> 5;
    int w = (blockIdx.x * blockDim.x + threadIdx.x) >> 5;
    int lane = threadIdx.x & 31;
    if (w >= NNODES) return;
    int off = g_off[w], end = g_off[w + 1];
    int deg = end - off;
    int cap = min(deg, MAXD);
    float ad0 = g_ald[2 * w], ad1 = g_ald[2 * w + 1];
    float as0 = g_als[2 * w], as1 = g_als[2 * w + 1];

    // phase A: stream edges -> smem (col, logit); running max
    float ls0 = lrelu(as0 + ad0), ls1 = lrelu(as1 + ad1);
    float m0 = ls0, m1 = ls1;
    for (int tt = lane; tt < deg; tt += 32) {
        int s = g_col[off + tt];
        float2 a = *(const float2*)(g_als + 2 * s);
        float l0 = lrelu(a.x + ad0), l1 = lrelu(a.y + ad1);
        if (tt < MAXD) { s_col[wip][tt] = s; s_ew[wip][tt] = make_float2(l0, l1); }
        m0 = fmaxf(m0, l0); m1 = fmaxf(m1, l1);
    }
#pragma unroll
    for (int o = 16; o; o >>= 1) {
        m0 = fmaxf(m0, __shfl_xor_sync(0xffffffffu, m0, o));
        m1 = fmaxf(m1, __shfl_xor_sync(0xffffffffu, m1, o));
    }
    __syncwarp();

    // phase B: exponentiate in smem, reduce denominator
    float d0 = 0.f, d1 = 0.f;
    for (int tt = lane; tt < cap; tt += 32) {
        float2 l = s_ew[wip][tt];
        float e0 = __expf(l.x - m0), e1 = __expf(l.y - m1);
        s_ew[wip][tt] = make_float2(e0, e1);
        d0 += e0; d1 += e1;
    }
#pragma unroll
    for (int o = 16; o; o >>= 1) {
        d0 += __shfl_xor_sync(0xffffffffu, d0, o);
        d1 += __shfl_xor_sync(0xffffffffu, d1, o);
    }
    __syncwarp();
    float es0 = __expf(ls0 - m0), es1 = __expf(ls1 - m1);
    float den0 = d0 + es0, den1 = d1 + es1;

    // phase C: unnormalized accumulation (self-loop first)
    float4 acc[R4];
    {
        const float4* hp = (const float4*)(h + (size_t)w * ld);
#pragma unroll
        for (int r = 0; r < R4; r++) {
            int c4 = lane + 32 * r;
            acc[r] = make_float4(0.f, 0.f, 0.f, 0.f);
            if (4 * c4 < ld) {
                float4 v = hp[c4];
                int c = 4 * c4;
                acc[r].x = (c     < C ? es0 : es1) * v.x;
                acc[r].y = (c + 1 < C ? es0 : es1) * v.y;
                acc[r].z = (c + 2 < C ? es0 : es1) * v.z;
                acc[r].w = (c + 3 < C ? es0 : es1) * v.w;
            }
        }
    }
    int t = 0;
    for (; t + EB <= cap; t += EB) {
        int cs[EB]; float2 ws[EB];
#pragma unroll
        for (int e = 0; e < EB; e++) { cs[e] = s_col[wip][t + e]; ws[e] = s_ew[wip][t + e]; }
        float4 v[EB][R4];
#pragma unroll
        for (int e = 0; e < EB; e++) {
            const float4* sp = (const float4*)(h + (size_t)cs[e] * ld);
#pragma unroll
            for (int r = 0; r < R4; r++) {
                int c4 = lane + 32 * r;
                v[e][r] = (4 * c4 < ld) ? sp[c4] : make_float4(0.f, 0.f, 0.f, 0.f);
            }
        }
#pragma unroll
        for (int e = 0; e < EB; e++) {
#pragma unroll
            for (int r = 0; r < R4; r++) {
                int c = 4 * (lane + 32 * r);
                acc[r].x = fmaf((c     < C ? ws[e].x : ws[e].y), v[e][r].x, acc[r].x);
                acc[r].y = fmaf((c + 1 < C ? ws[e].x : ws[e].y), v[e][r].y, acc[r].y);
                acc[r].z = fmaf((c + 2 < C ? ws[e].x : ws[e].y), v[e][r].z, acc[r].z);
                acc[r].w = fmaf((c + 3 < C ? ws[e].x : ws[e].y), v[e][r].w, acc[r].w);
            }
        }
    }
    for (; t < cap; t++) {
        int c0 = s_col[wip][t]; float2 ww = s_ew[wip][t];
        const float4* sp = (const float4*)(h + (size_t)c0 * ld);
#pragma unroll
        for (int r = 0; r < R4; r++) {
            int c4 = lane + 32 * r;
            if (4 * c4 < ld) {
                float4 vv = sp[c4];
                int c = 4 * c4;
                acc[r].x = fmaf((c     < C ? ww.x : ww.y), vv.x, acc[r].x);
                acc[r].y = fmaf((c + 1 < C ? ww.x : ww.y), vv.y, acc[r].y);
                acc[r].z = fmaf((c + 2 < C ? ww.x : ww.y), vv.z, acc[r].z);
                acc[r].w = fmaf((c + 3 < C ? ww.x : ww.y), vv.w, acc[r].w);
            }
        }
    }
    // overflow tail (deg > MAXD; statistically never, kept for correctness)
    for (int base = off + MAXD; base < end; base += 32) {
        int j = base + lane;
        int s = 0; float e0 = 0.f, e1 = 0.f;
        if (j < end) {
            s = g_col[j];
            float2 a = *(const float2*)(g_als + 2 * s);
            e0 = __expf(lrelu(a.x + ad0) - m0);
            e1 = __expf(lrelu(a.y + ad1) - m1);
        }
        int cnt = min(32, end - base);
        for (int q = 0; q < cnt; q++) {
            float w0 = __shfl_sync(0xffffffffu, e0, q);
            float w1 = __shfl_sync(0xffffffffu, e1, q);
            int   ss = __shfl_sync(0xffffffffu, s,  q);
            den0 += w0; den1 += w1;
            const float4* sp = (const float4*)(h + (size_t)ss * ld);
#pragma unroll
            for (int r = 0; r < R4; r++) {
                int c4 = lane + 32 * r;
                if (4 * c4 < ld) {
                    float4 vv = sp[c4];
                    int c = 4 * c4;
                    acc[r].x = fmaf((c     < C ? w0 : w1), vv.x, acc[r].x);
                    acc[r].y = fmaf((c + 1 < C ? w0 : w1), vv.y, acc[r].y);
                    acc[r].z = fmaf((c + 2 < C ? w0 : w1), vv.z, acc[r].z);
                    acc[r].w = fmaf((c + 3 < C ? w0 : w1), vv.w, acc[r].w);
                }
            }
        }
    }

    float i0 = 1.0f / den0, i1 = 1.0f / den1;
#pragma unroll
    for (int r = 0; r < R4; r++) {
        int c = 4 * (lane + 32 * r);
        float vv[4] = {acc[r].x, acc[r].y, acc[r].z, acc[r].w};
#pragma unroll
        for (int e = 0; e < 4; e++) {
            int cc = c + e;
            if (cc < HC) {
                float v = vv[e] * (cc < C ? i0 : i1) + bias[cc];
                __stcs(&out[(size_t)w * ld + cc], fmaxf(v, 0.f));
            }
        }
    }
}

// ---------------- launcher -------------------------------------------------
extern "C" void kernel_launch(void* const* d_in, const int* in_sizes, int n_in,
                              void* d_out, int out_size)
{
    const float* x   = (const float*)d_in[0];
    const int*   ei  = (const int*)d_in[1];
    const int*   src = ei;
    const int*   dst = ei + NEDGES;

    const float* W[4]  = {(const float*)d_in[3],  (const float*)d_in[7],
                          (const float*)d_in[11], (const float*)d_in[15]};
    const float* AS[4] = {(const float*)d_in[4],  (const float*)d_in[8],
                          (const float*)d_in[12], (const float*)d_in[16]};
    const float* AD[4] = {(const float*)d_in[5],  (const float*)d_in[9],
                          (const float*)d_in[13], (const float*)d_in[17]};
    const float* Bb[4] = {(const float*)d_in[6],  (const float*)d_in[10],
                          (const float*)d_in[14], (const float*)d_in[18]};
    const float* lw[4] = {(const float*)d_in[19], (const float*)d_in[21],
                          (const float*)d_in[23], (const float*)d_in[25]};
    const float* lb[4] = {(const float*)d_in[20], (const float*)d_in[22],
                          (const float*)d_in[24], (const float*)d_in[26]};

    float *H, *A, *ALS, *ALD, *WX;
    cudaGetSymbolAddress((void**)&H,   g_H);
    cudaGetSymbolAddress((void**)&A,   g_A);
    cudaGetSymbolAddress((void**)&ALS, g_als);
    cudaGetSymbolAddress((void**)&ALD, g_ald);
    cudaGetSymbolAddress((void**)&WX,  g_WxA);
    const size_t WXSTRIDE = 336 * 256;

    const int Cs[4]  = {125, 75, 50, 30};
    const int HCs[4] = {250, 150, 100, 60};
    const int lds[4] = {252, 152, 100, 60};
    const int Ks[4]  = {336, 250, 150, 100};
    const int ldi[4] = {336, 252, 152, 100};

    // --- setup (R12 ordering; GEMM-1 at profiled index 3) ---
    k_prep_all<<<(336 + 7) / 8, 256>>>(                                   // 0
        W[0], AS[0], AD[0], W[1], AS[1], AD[1],
        W[2], AS[2], AD[2], W[3], AS[3], AD[3]);
    k_count<<<NEDGES / 256, 256>>>(dst);                                  // 1
    k_scan<<<1, 1024>>>();                                                // 2
    k_sgemm<false, false><<<dim3(4, 256), 256>>>(                         // 3 (profiled)
        x, WX, nullptr, H, NNODES, HCs[0] + 4, Ks[0], ldi[0], HCs[0] + 4, lds[0],
        ALS, ALD, HCs[0]);
    k_fill<<<NEDGES / 256, 256>>>(src, dst);                              // 4
    k_agg<2><<<NNODES / 8, 256>>>(H, Bb[0], A, Cs[0], HCs[0], lds[0]);    // 5

    const float* in = A;
    for (int l = 1; l < 4; l++) {
        int C = Cs[l], HC = HCs[l], K = Ks[l], ld = lds[l], lin = ldi[l];
        k_sgemm<false, false><<<dim3((HC + 4 + 63) / 64, 256), 256>>>(
            in, WX + l * WXSTRIDE, nullptr, H, NNODES, HC + 4, K, lin, HC + 4, ld,
            ALS, ALD, HC);
        if (l == 1) k_agg<2><<<NNODES / 8, 256>>>(H, Bb[l], A, C, HC, ld);
        else        k_agg<1><<<NNODES / 8, 256>>>(H, Bb[l], A, C, HC, ld);
        in = A;
    }

    // --- MLP head: clean BM=64 small-tile GEMM, full-chip grids ---
    k_sgemm64<true><<<dim3(4, 128), 256>>>(
        A, lw[0], lb[0], H, 200, 480, 480, 200, 200);
    k_sgemm64<true><<<dim3(2, 128), 256>>>(
        H, lw[1], lb[1], A, 100, 200, 200, 100, 100);
    k_sgemm64<true><<<dim3(2, 128), 256>>>(
        A, lw[2], lb[2], H, 100, 100, 100, 100, 100);
    k_sgemm64<false><<<dim3(1, 128), 256>>>(
        H, lw[3], lb[3], (float*)d_out, 29, 100, 100, 29, 29);
}

// round 17
// speedup vs baseline: 1.2539x; 1.2539x over previous
#include <cuda_runtime.h>
#include <math.h>

#define NNODES 65536
#define NEDGES (NNODES * 16)
#define NEG 0.2f
#define MAXD 128   // per-warp edge cache; deg ~ Poisson(16), P(deg>128) ~ 0

// packed fp32x2 FMA (Blackwell FFMA2)
#define FMA2(d, a, b) asm("fma.rn.f32x2 %0, %1, %2, %0;" : "+l"(d) : "l"(a), "l"(b))
#define PACK2(d, s)   asm("mov.b64 %0, {%1, %1};" : "=l"(d) : "f"(s))

// ---------------- scratch (static device globals; no runtime alloc) --------
__device__ __align__(16) float g_H[NNODES * 256];
__device__ __align__(16) float g_A[NNODES * 256];
__device__ __align__(8)  float g_als[NNODES * 2];
__device__ __align__(8)  float g_ald[NNODES * 2];
__device__ __align__(16) float g_WxA[4][336 * 256];  // per-layer extended weights
__device__ int g_cnt[NNODES];          // zero-init at load; k_scan re-zeroes each call
__device__ int g_off[NNODES + 1];
__device__ int g_cur[NNODES];
__device__ int g_col[NEDGES];

// ---------------- CSR build ------------------------------------------------
__global__ void k_count(const int* __restrict__ dst) {
    int e = blockIdx.x * blockDim.x + threadIdx.x;
    if (e < NEDGES) atomicAdd(&g_cnt[dst[e]], 1);
}

// exclusive scan of counts; seeds g_cur; self-clears g_cnt for the next replay
__global__ void k_scan() {
    __shared__ int ss[1024];
    int t = threadIdx.x;
    int base = t * 64;
    int s = 0;
#pragma unroll 8
    for (int i = 0; i < 64; i++) s += g_cnt[base + i];
    ss[t] = s;
    __syncthreads();
    for (int d = 1; d < 1024; d <<= 1) {
        int v = (t >= d) ? ss[t - d] : 0;
        __syncthreads();
        ss[t] += v;
        __syncthreads();
    }
    int run = (t == 0) ? 0 : ss[t - 1];
    for (int i = 0; i < 64; i++) {
        g_off[base + i] = run;
        g_cur[base + i] = run;
        run += g_cnt[base + i];
        g_cnt[base + i] = 0;          // self-clear for next graph replay
    }
    if (t == 1023) g_off[NNODES] = run;
}

__global__ void k_fill(const int* __restrict__ src, const int* __restrict__ dst) {
    int e = blockIdx.x * blockDim.x + threadIdx.x;
    if (e < NEDGES) {
        int d = dst[e];
        int p = atomicAdd(&g_cur[d], 1);
        g_col[p] = src[e];
    }
}

// ---------------- all-layer W-extension prep: Wx_l = [W_l | W@as | W@ad] ---
__global__ void k_prep_all(
    const float* __restrict__ W0, const float* __restrict__ as0, const float* __restrict__ ad0,
    const float* __restrict__ W1, const float* __restrict__ as1, const float* __restrict__ ad1,
    const float* __restrict__ W2, const float* __restrict__ as2, const float* __restrict__ ad2,
    const float* __restrict__ W3, const float* __restrict__ as3, const float* __restrict__ ad3)
{
    const float* Ws[4] = {W0, W1, W2, W3};
    const float* As[4] = {as0, as1, as2, as3};
    const float* Ad[4] = {ad0, ad1, ad2, ad3};
    const int Ks[4] = {336, 250, 150, 100};
    const int Cs[4] = {125, 75, 50, 30};
    int k = (blockIdx.x * blockDim.x + threadIdx.x) >> 5;
    int lane = threadIdx.x & 31;
#pragma unroll
    for (int l = 0; l < 4; l++) {
        if (k >= Ks[l]) continue;
        int C = Cs[l], HC = 2 * C;
        const float* wp = Ws[l] + (size_t)k * HC;
        float* xp = g_WxA[l] + (size_t)k * (HC + 4);
        float s0 = 0, s1 = 0, d0 = 0, d1 = 0;
        for (int c = lane; c < HC; c += 32) {
            float wv = wp[c];
            xp[c] = wv;
            float a = As[l][c], b = Ad[l][c];
            if (c < C) { s0 = fmaf(wv, a, s0); d0 = fmaf(wv, b, d0); }
            else       { s1 = fmaf(wv, a, s1); d1 = fmaf(wv, b, d1); }
        }
#pragma unroll
        for (int o = 16; o; o >>= 1) {
            s0 += __shfl_xor_sync(0xffffffffu, s0, o);
            s1 += __shfl_xor_sync(0xffffffffu, s1, o);
            d0 += __shfl_xor_sync(0xffffffffu, d0, o);
            d1 += __shfl_xor_sync(0xffffffffu, d1, o);
        }
        if (lane == 0) {
            xp[HC] = s0; xp[HC + 1] = s1; xp[HC + 2] = d0; xp[HC + 3] = d1;
        }
    }
}

// ---------------- SGEMM, FFMA2, 16x4 per-thread tile (R12 champion) --------
// Columns >= NH are attention-logit columns, routed to g_als / g_ald.
template <bool RELU, bool BIAS>
__global__ void __launch_bounds__(256) k_sgemm(
    const float* __restrict__ A, const float* __restrict__ B,
    const float* __restrict__ bias, float* __restrict__ C,
    int M, int N, int K, int lda, int ldb, int ldc,
    float* als, float* ald, int NH)
{
    constexpr int BM = 256, BN = 64, BK = 16, ASTR = 260;
    __shared__ float As[BK * ASTR];
    __shared__ float Bs[BK * BN];

    int tid = threadIdx.x;
    int tx = tid & 15;
    int ty = tid >> 4;
    int bm = blockIdx.y * BM;
    int bn = blockIdx.x * BN;
    int kq = tid & 3, ma = tid >> 2;

    unsigned long long acc[8][4];
#pragma unroll
    for (int i = 0; i < 8; i++)
#pragma unroll
        for (int j = 0; j < 4; j++) acc[i][j] = 0ull;

    int ntiles = (K + BK - 1) / BK;
    float4 pa[4];
    float pb[4];

    {
        int kk = kq * 4;
#pragma unroll
        for (int r = 0; r < 4; r++) {
            int row = bm + ma + r * 64;
            if (kk + 3 < K) {
                pa[r] = __ldcs((const float4*)(A + (size_t)row * lda + kk));
            } else {
                float4 v = make_float4(0.f, 0.f, 0.f, 0.f);
                if (kk     < K) v.x = __ldcs(A + (size_t)row * lda + kk);
                if (kk + 1 < K) v.y = __ldcs(A + (size_t)row * lda + kk + 1);
                if (kk + 2 < K) v.z = __ldcs(A + (size_t)row * lda + kk + 2);
                pa[r] = v;
            }
        }
#pragma unroll
        for (int i = 0; i < 4; i++) {
            int idx = tid + i * 256;
            int n = idx & 63, k = idx >> 6;
            int col = bn + n;
            pb[i] = (k < K && col < N) ? B[(size_t)k * ldb + col] : 0.f;
        }
    }

    for (int t = 0; t < ntiles; t++) {
        __syncthreads();
#pragma unroll
        for (int r = 0; r < 4; r++) {
            float v[4] = {pa[r].x, pa[r].y, pa[r].z, pa[r].w};
#pragma unroll
            for (int j = 0; j < 4; j++)
                As[(kq * 4 + j) * ASTR + ma + r * 64] = v[j];
        }
#pragma unroll
        for (int i = 0; i < 4; i++) {
            int idx = tid + i * 256;
            Bs[(idx >> 6) * BN + (idx & 63)] = pb[i];
        }
        __syncthreads();

        if (t + 1 < ntiles) {
            int kk = (t + 1) * BK + kq * 4;
#pragma unroll
            for (int r = 0; r < 4; r++) {
                int row = bm + ma + r * 64;
                if (kk + 3 < K) {
                    pa[r] = __ldcs((const float4*)(A + (size_t)row * lda + kk));
                } else {
                    float4 v = make_float4(0.f, 0.f, 0.f, 0.f);
                    if (kk     < K) v.x = __ldcs(A + (size_t)row * lda + kk);
                    if (kk + 1 < K) v.y = __ldcs(A + (size_t)row * lda + kk + 1);
                    if (kk + 2 < K) v.z = __ldcs(A + (size_t)row * lda + kk + 2);
                    pa[r] = v;
                }
            }
#pragma unroll
            for (int i = 0; i < 4; i++) {
                int idx = tid + i * 256;
                int n = idx & 63, k = (t + 1) * BK + (idx >> 6);
                int col = bn + n;
                pb[i] = (k < K && col < N) ? B[(size_t)k * ldb + col] : 0.f;
            }
        }

#pragma unroll
        for (int kk = 0; kk < BK; kk++) {
            const ulonglong2* ap = (const ulonglong2*)&As[kk * ASTR + ty * 16];
            unsigned long long aa[8];
#pragma unroll
            for (int q = 0; q < 4; q++) {
                ulonglong2 u = ap[q];
                aa[2 * q] = u.x; aa[2 * q + 1] = u.y;
            }
            float4 b4 = *(const float4*)&Bs[kk * BN + tx * 4];
            unsigned long long bb[4];
            PACK2(bb[0], b4.x); PACK2(bb[1], b4.y);
            PACK2(bb[2], b4.z); PACK2(bb[3], b4.w);
#pragma unroll
            for (int i = 0; i < 8; i++)
#pragma unroll
                for (int j = 0; j < 4; j++)
                    FMA2(acc[i][j], aa[i], bb[j]);
        }
    }

#pragma unroll
    for (int i = 0; i < 8; i++) {
#pragma unroll
        for (int j = 0; j < 4; j++) {
            int col = bn + tx * 4 + j;
            if (col < N) {
                float lo = __uint_as_float((unsigned)(acc[i][j] & 0xffffffffull));
                float hi = __uint_as_float((unsigned)(acc[i][j] >> 32));
                int row = bm + ty * 16 + 2 * i;
                if (col < NH) {
                    float bv = BIAS ? bias[col] : 0.f;
                    float v0 = lo + bv, v1 = hi + bv;
                    if (RELU) { v0 = fmaxf(v0, 0.f); v1 = fmaxf(v1, 0.f); }
                    C[(size_t)row * ldc + col]       = v0;
                    C[(size_t)(row + 1) * ldc + col] = v1;
                } else {
                    int q = col - NH;             // 0,1 -> als ; 2,3 -> ald
                    float* dp = (q < 2) ? als : ald;
                    int h = q & 1;
                    dp[2 * row + h]       = lo;
                    dp[2 * (row + 1) + h] = hi;
                }
            }
        }
    }
}

__device__ __forceinline__ float lrelu(float x) { return x > 0.f ? x : NEG * x; }

// ---------------- aggregation: smem edge cache (R12 champion config) -------
template <int R4>
__global__ void __launch_bounds__(256) k_agg(
    const float* __restrict__ h, const float* __restrict__ bias,
    float* __restrict__ out, int C, int HC, int ld)
{
    constexpr int EB = (R4 == 1) ? 8 : 4;   // edges per batch (proven sweet spot)
    __shared__ float2 s_ew[8][MAXD];
    __shared__ int    s_col[8][MAXD];
    int wip = threadIdx.x >> 5;
    int w = (blockIdx.x * blockDim.x + threadIdx.x) >> 5;
    int lane = threadIdx.x & 31;
    if (w >= NNODES) return;
    int off = g_off[w], end = g_off[w + 1];
    int deg = end - off;
    int cap = min(deg, MAXD);
    float ad0 = g_ald[2 * w], ad1 = g_ald[2 * w + 1];
    float as0 = g_als[2 * w], as1 = g_als[2 * w + 1];

    // phase A: stream edges -> smem (col, logit); running max
    float ls0 = lrelu(as0 + ad0), ls1 = lrelu(as1 + ad1);
    float m0 = ls0, m1 = ls1;
    for (int tt = lane; tt < deg; tt += 32) {
        int s = g_col[off + tt];
        float2 a = *(const float2*)(g_als + 2 * s);
        float l0 = lrelu(a.x + ad0), l1 = lrelu(a.y + ad1);
        if (tt < MAXD) { s_col[wip][tt] = s; s_ew[wip][tt] = make_float2(l0, l1); }
        m0 = fmaxf(m0, l0); m1 = fmaxf(m1, l1);
    }
#pragma unroll
    for (int o = 16; o; o >>= 1) {
        m0 = fmaxf(m0, __shfl_xor_sync(0xffffffffu, m0, o));
        m1 = fmaxf(m1, __shfl_xor_sync(0xffffffffu, m1, o));
    }
    __syncwarp();

    // phase B: exponentiate in smem, reduce denominator
    float d0 = 0.f, d1 = 0.f;
    for (int tt = lane; tt < cap; tt += 32) {
        float2 l = s_ew[wip][tt];
        float e0 = __expf(l.x - m0), e1 = __expf(l.y - m1);
        s_ew[wip][tt] = make_float2(e0, e1);
        d0 += e0; d1 += e1;
    }
#pragma unroll
    for (int o = 16; o; o >>= 1) {
        d0 += __shfl_xor_sync(0xffffffffu, d0, o);
        d1 += __shfl_xor_sync(0xffffffffu, d1, o);
    }
    __syncwarp();
    float es0 = __expf(ls0 - m0), es1 = __expf(ls1 - m1);
    float den0 = d0 + es0, den1 = d1 + es1;

    // phase C: unnormalized accumulation (self-loop first)
    float4 acc[R4];
    {
        const float4* hp = (const float4*)(h + (size_t)w * ld);
#pragma unroll
        for (int r = 0; r < R4; r++) {
            int c4 = lane + 32 * r;
            acc[r] = make_float4(0.f, 0.f, 0.f, 0.f);
            if (4 * c4 < ld) {
                float4 v = hp[c4];
                int c = 4 * c4;
                acc[r].x = (c     < C ? es0 : es1) * v.x;
                acc[r].y = (c + 1 < C ? es0 : es1) * v.y;
                acc[r].z = (c + 2 < C ? es0 : es1) * v.z;
                acc[r].w = (c + 3 < C ? es0 : es1) * v.w;
            }
        }
    }
    int t = 0;
    for (; t + EB <= cap; t += EB) {
        int cs[EB]; float2 ws[EB];
#pragma unroll
        for (int e = 0; e < EB; e++) { cs[e] = s_col[wip][t + e]; ws[e] = s_ew[wip][t + e]; }
        float4 v[EB][R4];
#pragma unroll
        for (int e = 0; e < EB; e++) {
            const float4* sp = (const float4*)(h + (size_t)cs[e] * ld);
#pragma unroll
            for (int r = 0; r < R4; r++) {
                int c4 = lane + 32 * r;
                v[e][r] = (4 * c4 < ld) ? sp[c4] : make_float4(0.f, 0.f, 0.f, 0.f);
            }
        }
#pragma unroll
        for (int e = 0; e < EB; e++) {
#pragma unroll
            for (int r = 0; r < R4; r++) {
                int c = 4 * (lane + 32 * r);
                acc[r].x = fmaf((c     < C ? ws[e].x : ws[e].y), v[e][r].x, acc[r].x);
                acc[r].y = fmaf((c + 1 < C ? ws[e].x : ws[e].y), v[e][r].y, acc[r].y);
                acc[r].z = fmaf((c + 2 < C ? ws[e].x : ws[e].y), v[e][r].z, acc[r].z);
                acc[r].w = fmaf((c + 3 < C ? ws[e].x : ws[e].y), v[e][r].w, acc[r].w);
            }
        }
    }
    for (; t < cap; t++) {
        int c0 = s_col[wip][t]; float2 ww = s_ew[wip][t];
        const float4* sp = (const float4*)(h + (size_t)c0 * ld);
#pragma unroll
        for (int r = 0; r < R4; r++) {
            int c4 = lane + 32 * r;
            if (4 * c4 < ld) {
                float4 vv = sp[c4];
                int c = 4 * c4;
                acc[r].x = fmaf((c     < C ? ww.x : ww.y), vv.x, acc[r].x);
                acc[r].y = fmaf((c + 1 < C ? ww.x : ww.y), vv.y, acc[r].y);
                acc[r].z = fmaf((c + 2 < C ? ww.x : ww.y), vv.z, acc[r].z);
                acc[r].w = fmaf((c + 3 < C ? ww.x : ww.y), vv.w, acc[r].w);
            }
        }
    }
    // overflow tail (deg > MAXD; statistically never, kept for correctness)
    for (int base = off + MAXD; base < end; base += 32) {
        int j = base + lane;
        int s = 0; float e0 = 0.f, e1 = 0.f;
        if (j < end) {
            s = g_col[j];
            float2 a = *(const float2*)(g_als + 2 * s);
            e0 = __expf(lrelu(a.x + ad0) - m0);
            e1 = __expf(lrelu(a.y + ad1) - m1);
        }
        int cnt = min(32, end - base);
        for (int q = 0; q < cnt; q++) {
            float w0 = __shfl_sync(0xffffffffu, e0, q);
            float w1 = __shfl_sync(0xffffffffu, e1, q);
            int   ss = __shfl_sync(0xffffffffu, s,  q);
            den0 += w0; den1 += w1;
            const float4* sp = (const float4*)(h + (size_t)ss * ld);
#pragma unroll
            for (int r = 0; r < R4; r++) {
                int c4 = lane + 32 * r;
                if (4 * c4 < ld) {
                    float4 vv = sp[c4];
                    int c = 4 * c4;
                    acc[r].x = fmaf((c     < C ? w0 : w1), vv.x, acc[r].x);
                    acc[r].y = fmaf((c + 1 < C ? w0 : w1), vv.y, acc[r].y);
                    acc[r].z = fmaf((c + 2 < C ? w0 : w1), vv.z, acc[r].z);
                    acc[r].w = fmaf((c + 3 < C ? w0 : w1), vv.w, acc[r].w);
                }
            }
        }
    }

    float i0 = 1.0f / den0, i1 = 1.0f / den1;
#pragma unroll
    for (int r = 0; r < R4; r++) {
        int c = 4 * (lane + 32 * r);
        float vv[4] = {acc[r].x, acc[r].y, acc[r].z, acc[r].w};
#pragma unroll
        for (int e = 0; e < 4; e++) {
            int cc = c + e;
            if (cc < HC) {
                float v = vv[e] * (cc < C ? i0 : i1) + bias[cc];
                __stcs(&out[(size_t)w * ld + cc], fmaxf(v, 0.f));
            }
        }
    }
}

// ---------------- launcher -------------------------------------------------
// Side-stream handles: created once (resource handles only; the captured work
// is identical on every call — no device-memory allocation involved).
static cudaStream_t g_s2 = nullptr;
static cudaEvent_t  g_evFork = nullptr, g_evJoin = nullptr;

extern "C" void kernel_launch(void* const* d_in, const int* in_sizes, int n_in,
                              void* d_out, int out_size)
{
    const float* x   = (const float*)d_in[0];
    const int*   ei  = (const int*)d_in[1];
    const int*   src = ei;
    const int*   dst = ei + NEDGES;

    const float* W[4]  = {(const float*)d_in[3],  (const float*)d_in[7],
                          (const float*)d_in[11], (const float*)d_in[15]};
    const float* AS[4] = {(const float*)d_in[4],  (const float*)d_in[8],
                          (const float*)d_in[12], (const float*)d_in[16]};
    const float* AD[4] = {(const float*)d_in[5],  (const float*)d_in[9],
                          (const float*)d_in[13], (const float*)d_in[17]};
    const float* Bb[4] = {(const float*)d_in[6],  (const float*)d_in[10],
                          (const float*)d_in[14], (const float*)d_in[18]};
    const float* lw[4] = {(const float*)d_in[19], (const float*)d_in[21],
                          (const float*)d_in[23], (const float*)d_in[25]};
    const float* lb[4] = {(const float*)d_in[20], (const float*)d_in[22],
                          (const float*)d_in[24], (const float*)d_in[26]};

    float *H, *A, *ALS, *ALD, *WX;
    cudaGetSymbolAddress((void**)&H,   g_H);
    cudaGetSymbolAddress((void**)&A,   g_A);
    cudaGetSymbolAddress((void**)&ALS, g_als);
    cudaGetSymbolAddress((void**)&ALD, g_ald);
    cudaGetSymbolAddress((void**)&WX,  g_WxA);
    const size_t WXSTRIDE = 336 * 256;

    if (!g_s2) {
        cudaStreamCreateWithFlags(&g_s2, cudaStreamNonBlocking);
        cudaEventCreateWithFlags(&g_evFork, cudaEventDisableTiming);
        cudaEventCreateWithFlags(&g_evJoin, cudaEventDisableTiming);
    }

    const int Cs[4]  = {125, 75, 50, 30};
    const int HCs[4] = {250, 150, 100, 60};
    const int lds[4] = {252, 152, 100, 60};
    const int Ks[4]  = {336, 250, 150, 100};
    const int ldi[4] = {336, 252, 152, 100};

    // --- fork: CSR build on side stream, overlapped with prep + GEMM-1 ---
    cudaEventRecord(g_evFork, 0);
    cudaStreamWaitEvent(g_s2, g_evFork, 0);
    k_count<<<NEDGES / 256, 256, 0, g_s2>>>(dst);
    k_scan<<<1, 1024, 0, g_s2>>>();
    k_fill<<<NEDGES / 256, 256, 0, g_s2>>>(src, dst);
    cudaEventRecord(g_evJoin, g_s2);

    k_prep_all<<<(336 + 7) / 8, 256>>>(
        W[0], AS[0], AD[0], W[1], AS[1], AD[1],
        W[2], AS[2], AD[2], W[3], AS[3], AD[3]);
    k_sgemm<false, false><<<dim3(4, 256), 256>>>(
        x, WX, nullptr, H, NNODES, HCs[0] + 4, Ks[0], ldi[0], HCs[0] + 4, lds[0],
        ALS, ALD, HCs[0]);

    // --- join: aggregation needs both the CSR and the GEMM/logits ---
    cudaStreamWaitEvent(0, g_evJoin, 0);
    k_agg<2><<<NNODES / 8, 256>>>(H, Bb[0], A, Cs[0], HCs[0], lds[0]);

    const float* in = A;
    for (int l = 1; l < 4; l++) {
        int C = Cs[l], HC = HCs[l], K = Ks[l], ld = lds[l], lin = ldi[l];
        k_sgemm<false, false><<<dim3((HC + 4 + 63) / 64, 256), 256>>>(
            in, WX + l * WXSTRIDE, nullptr, H, NNODES, HC + 4, K, lin, HC + 4, ld,
            ALS, ALD, HC);
        if (l == 1) k_agg<2><<<NNODES / 8, 256>>>(H, Bb[l], A, C, HC, ld);
        else        k_agg<1><<<NNODES / 8, 256>>>(H, Bb[l], A, C, HC, ld);
        in = A;
    }

    // --- MLP head: R12 grids, BM=256 (A is 8192 x 480 contiguous) ---
    k_sgemm<true, true><<<dim3(4, 32), 256>>>(
        A, lw[0], lb[0], H, 8192, 200, 480, 480, 200, 200, nullptr, nullptr, 200);
    k_sgemm<true, true><<<dim3(2, 32), 256>>>(
        H, lw[1], lb[1], A, 8192, 100, 200, 200, 100, 100, nullptr, nullptr, 100);
    k_sgemm<true, true><<<dim3(2, 32), 256>>>(
        A, lw[2], lb[2], H, 8192, 100, 100, 100, 100, 100, nullptr, nullptr, 100);
    k_sgemm<false, true><<<dim3(1, 32), 256>>>(
        H, lw[3], lb[3], (float*)d_out, 8192, 29, 100, 100, 29, 29, nullptr, nullptr, 29);
}